// round 15
// baseline (speedup 1.0000x reference)
#include <cuda_runtime.h>
#include <cuda_bf16.h>
#include <float.h>
#include <stdint.h>

#define NB    16384
#define NPTS  2048
#define BATCH 8
#define KNN   20
#define NEG_SLOPE 0.2f

// ---------------- scratch (device globals) ----------------------------------
__device__ float g_X1[NB * 64];
__device__ float g_X2[NB * 64];
__device__ float g_X3[NB * 128];
__device__ float g_X4[NB * 256];
__device__ float g_PC[NB * 512];
__device__ float g_G[(size_t)BATCH * NPTS * NPTS];   // holds negd
__device__ float g_xx[NB];
__device__ int   g_idx[NB * KNN];
__device__ __nv_bfloat16 g_XexpA[(size_t)NB * 512];  // 4-term A-form [hi|hi|lo|lo]
__device__ __nv_bfloat16 g_XexpB[(size_t)NB * 512];  // 4-term B-form [hi|lo|hi|lo]
__device__ __nv_bfloat16 g_WcExp[512 * 512];         // 4-term B-form of Wc^T
__device__ __nv_bfloat16 g_CATexp[(size_t)NB * 1536];
__device__ __nv_bfloat16 g_W5exp[(size_t)1024 * 1536];

// ======================= warp-MMA helpers (plain PTX, sm_80+) ================
__device__ __forceinline__ uint32_t smem_u32(const void* p) {
    uint32_t a;
    asm("{ .reg .u64 t; cvta.to.shared.u64 t, %1; cvt.u32.u64 %0, t; }"
        : "=r"(a) : "l"(p));
    return a;
}

#define SWZ(o) ((o) ^ (((o) >> 3) & 0x70))

#define LDSM4(r, a) \
    asm volatile("ldmatrix.sync.aligned.m8n8.x4.shared.b16 {%0,%1,%2,%3}, [%4];" \
        : "=r"((r)[0]), "=r"((r)[1]), "=r"((r)[2]), "=r"((r)[3]) : "r"(a))

#define MMA16816(d, a, b0, b1) \
    asm volatile("mma.sync.aligned.m16n8k16.row.col.f32.bf16.bf16.f32 " \
        "{%0,%1,%2,%3},{%4,%5,%6,%7},{%8,%9},{%0,%1,%2,%3};" \
        : "+f"((d)[0]), "+f"((d)[1]), "+f"((d)[2]), "+f"((d)[3]) \
        : "r"((a)[0]), "r"((a)[1]), "r"((a)[2]), "r"((a)[3]), "r"(b0), "r"(b1))

#define STAGE_B 16384                      // 128 rows x 128 bytes
#define W5_SMEM (4 * STAGE_B + 128)        // 2 stages x 2 operands
#define TILE_PITCH 133
#define GR_SMEM (128 * TILE_PITCH * 4 + 256)  // transpose tile dominates

// mainloop: acc += A(128 x 64*kc) * B(128 x 64*kc)^T, both row-major bf16
__device__ __forceinline__ void hmma_loop(char* sm, const char* Ag, const char* Bg,
                                          size_t strA, size_t strB, int kchunks,
                                          int tid, float acc[2][8][4]) {
    char* sA = sm;
    char* sB = sm + 2 * STAGE_B;
    int lane = tid & 31, wid = tid >> 5;
    int wm = wid & 3, wn = wid >> 2;
    int r = tid >> 3, cbyte = (tid & 7) * 16;
    #pragma unroll
    for (int i = 0; i < 4; i++) {
        int row = r + 32 * i;
        *(uint4*)(sA + SWZ(row * 128 + cbyte)) = *(const uint4*)(Ag + (size_t)row * strA + cbyte);
        *(uint4*)(sB + SWZ(row * 128 + cbyte)) = *(const uint4*)(Bg + (size_t)row * strB + cbyte);
    }
    __syncthreads();
    uint32_t sA32 = smem_u32(sA), sB32 = smem_u32(sB);
    int buf = 0;
    for (int c = 0; c < kchunks; c++) {
        uint4 pa[4], pb[4];
        if (c + 1 < kchunks) {
            const char* An = Ag + (size_t)(c + 1) * 128;
            const char* Bn = Bg + (size_t)(c + 1) * 128;
            #pragma unroll
            for (int i = 0; i < 4; i++) {
                int row = r + 32 * i;
                pa[i] = *(const uint4*)(An + (size_t)row * strA + cbyte);
                pb[i] = *(const uint4*)(Bn + (size_t)row * strB + cbyte);
            }
        }
        uint32_t aB = sA32 + buf * STAGE_B, bB = sB32 + buf * STAGE_B;
        #pragma unroll
        for (int ks = 0; ks < 4; ks++) {
            uint32_t a[2][4], b[4][4];
            #pragma unroll
            for (int mi = 0; mi < 2; mi++) {
                int row = wm * 32 + mi * 16 + (lane & 15);
                int off = row * 128 + ks * 32 + ((lane >> 4) << 4);
                LDSM4(a[mi], aB + SWZ(off));
            }
            #pragma unroll
            for (int np = 0; np < 4; np++) {
                int row = wn * 64 + np * 16 + ((lane >> 4) << 3) + (lane & 7);
                int off = row * 128 + ks * 32 + (((lane >> 3) & 1) << 4);
                LDSM4(b[np], bB + SWZ(off));
            }
            #pragma unroll
            for (int mi = 0; mi < 2; mi++)
                #pragma unroll
                for (int nj = 0; nj < 8; nj++)
                    MMA16816(acc[mi][nj], a[mi], b[nj >> 1][(nj & 1) * 2], b[nj >> 1][(nj & 1) * 2 + 1]);
        }
        if (c + 1 < kchunks) {
            char* dA = sA + (buf ^ 1) * STAGE_B;
            char* dB = sB + (buf ^ 1) * STAGE_B;
            #pragma unroll
            for (int i = 0; i < 4; i++) {
                int row = r + 32 * i;
                *(uint4*)(dA + SWZ(row * 128 + cbyte)) = pa[i];
                *(uint4*)(dB + SWZ(row * 128 + cbyte)) = pb[i];
            }
            __syncthreads();
            buf ^= 1;
        }
    }
}

// --------- Gram (triangular blocks): negd = 2*X@X^T - xx_m - xx_n ------------
__global__ void __launch_bounds__(256) gram_hmma(const __nv_bfloat16* __restrict__ Ae,
                                                 const __nv_bfloat16* __restrict__ Be,
                                                 const float* __restrict__ xx,
                                                 float* __restrict__ negd, int Kexp) {
    extern __shared__ char dsm[];
    uint32_t sb = smem_u32(dsm);
    char* sm = dsm + (((sb + 127) & ~127u) - sb);
    int tid = threadIdx.x, lane = tid & 31, wid = tid >> 5;
    int wm = wid & 3, wn = wid >> 2;
    int b = blockIdx.z;
    int rem = blockIdx.x, ti = 0;
    while (rem >= 16 - ti) { rem -= 16 - ti; ti++; }
    int tj = ti + rem;
    int m0 = ti * 128, n0 = tj * 128;

    float acc[2][8][4] = {};
    size_t str = (size_t)Kexp * 2;
    hmma_loop(sm, (const char*)(Ae + (size_t)(b * NPTS + m0) * Kexp),
                  (const char*)(Be + (size_t)(b * NPTS + n0) * Kexp),
              str, str, Kexp >> 6, tid, acc);

    const float* xxb = xx + b * NPTS;
    float* nd = negd + ((size_t)b << 22);
    float (*tile)[TILE_PITCH] = (float(*)[TILE_PITCH])sm;

    if (ti != tj) __syncthreads();

    #pragma unroll
    for (int mi = 0; mi < 2; mi++) {
        int lm0 = wm * 32 + mi * 16 + (lane >> 2);
        int rowa = m0 + lm0;
        float xm0 = __ldg(&xxb[rowa]), xm1 = __ldg(&xxb[rowa + 8]);
        #pragma unroll
        for (int nj = 0; nj < 8; nj++) {
            int ln = wn * 64 + nj * 8 + (lane & 3) * 2;
            int col = n0 + ln;
            float xn0 = __ldg(&xxb[col]), xn1 = __ldg(&xxb[col + 1]);
            float v00 = 2.f * acc[mi][nj][0] - xm0 - xn0;
            float v01 = 2.f * acc[mi][nj][1] - xm0 - xn1;
            float v10 = 2.f * acc[mi][nj][2] - xm1 - xn0;
            float v11 = 2.f * acc[mi][nj][3] - xm1 - xn1;
            *(float2*)&nd[(size_t)rowa * NPTS + col]       = make_float2(v00, v01);
            *(float2*)&nd[(size_t)(rowa + 8) * NPTS + col] = make_float2(v10, v11);
            if (ti != tj) {
                tile[lm0][ln]         = v00;
                tile[lm0][ln + 1]     = v01;
                tile[lm0 + 8][ln]     = v10;
                tile[lm0 + 8][ln + 1] = v11;
            }
        }
    }
    if (ti != tj) {
        __syncthreads();
        int nn = tid >> 1;
        int mmBase = (tid & 1) * 64;
        size_t gbase = (size_t)(n0 + nn) * NPTS + m0 + mmBase;
        #pragma unroll
        for (int k4 = 0; k4 < 16; k4++) {
            int mm = mmBase + k4 * 4;
            float4 w = make_float4(tile[mm][nn], tile[mm + 1][nn],
                                   tile[mm + 2][nn], tile[mm + 3][nn]);
            *(float4*)&nd[gbase + k4 * 4] = w;
        }
    }
}

// --------- W5: out = lrelu(cat@W5 * g + b), transposed store -----------------
__global__ void __launch_bounds__(256) w5_hmma(const __nv_bfloat16* __restrict__ Ae,
                                               const __nv_bfloat16* __restrict__ Be,
                                               const float* __restrict__ g,
                                               const float* __restrict__ bias,
                                               float* __restrict__ out) {
    extern __shared__ char dsm[];
    uint32_t sb = smem_u32(dsm);
    char* sm = dsm + (((sb + 127) & ~127u) - sb);
    int tid = threadIdx.x, lane = tid & 31, wid = tid >> 5;
    int wm = wid & 3, wn = wid >> 2;
    int m0 = blockIdx.y * 128, n0 = blockIdx.x * 128;

    float acc[2][8][4] = {};
    hmma_loop(sm, (const char*)(Ae + (size_t)m0 * 1536),
                  (const char*)(Be + (size_t)n0 * 1536),
              3072, 3072, 24, tid, acc);

    #pragma unroll
    for (int mi = 0; mi < 2; mi++) {
        int m = m0 + wm * 32 + mi * 16 + (lane >> 2);
        #pragma unroll
        for (int half = 0; half < 2; half++) {
            int mr = m + half * 8;
            int bidx = mr >> 11, npt = mr & 2047;
            size_t obase = ((size_t)bidx << 10) * NPTS + npt;
            #pragma unroll
            for (int nj = 0; nj < 8; nj++) {
                int col = n0 + wn * 64 + nj * 8 + (lane & 3) * 2;
                float g0 = __ldg(&g[col]), g1 = __ldg(&g[col + 1]);
                float b0 = __ldg(&bias[col]), b1 = __ldg(&bias[col + 1]);
                float z0 = fmaf(acc[mi][nj][half * 2],     g0, b0);
                float z1 = fmaf(acc[mi][nj][half * 2 + 1], g1, b1);
                out[obase + (size_t)col * NPTS]       = z0 >= 0.f ? z0 : NEG_SLOPE * z0;
                out[obase + (size_t)(col + 1) * NPTS] = z1 >= 0.f ? z1 : NEG_SLOPE * z1;
            }
        }
    }
}

// --------- PC: PC = X @ [W_a | W_b - W_a]  (HMMA bf16x4 exact, fp32 store) ---
__global__ void __launch_bounds__(256) pc_hmma(const __nv_bfloat16* __restrict__ Ae,
                                               const __nv_bfloat16* __restrict__ Be,
                                               float* __restrict__ PC,
                                               int N, int Kexp) {
    extern __shared__ char dsm[];
    uint32_t sb = smem_u32(dsm);
    char* sm = dsm + (((sb + 127) & ~127u) - sb);
    int tid = threadIdx.x, lane = tid & 31, wid = tid >> 5;
    int wm = wid & 3, wn = wid >> 2;
    int m0 = blockIdx.y * 128, n0 = blockIdx.x * 128;

    float acc[2][8][4] = {};
    size_t str = (size_t)Kexp * 2;
    hmma_loop(sm, (const char*)(Ae + (size_t)m0 * Kexp),
                  (const char*)(Be + (size_t)n0 * Kexp),
              str, str, Kexp >> 6, tid, acc);

    #pragma unroll
    for (int mi = 0; mi < 2; mi++) {
        int m = m0 + wm * 32 + mi * 16 + (lane >> 2);
        #pragma unroll
        for (int nj = 0; nj < 8; nj++) {
            int col = n0 + wn * 64 + nj * 8 + (lane & 3) * 2;
            *(float2*)&PC[(size_t)m * N + col]       = make_float2(acc[mi][nj][0], acc[mi][nj][1]);
            *(float2*)&PC[(size_t)(m + 8) * N + col] = make_float2(acc[mi][nj][2], acc[mi][nj][3]);
        }
    }
}

// ---------------- expansion kernels (bf16x4 exact split) ---------------------
// A-form of X: [hi|hi|lo|lo], zero-padded to Kexp
__global__ void expand_px(const float* __restrict__ X, __nv_bfloat16* __restrict__ Ae,
                          int K, int Kexp) {
    long long i = (long long)blockIdx.x * 256 + threadIdx.x;
    if (i >= (long long)NB * Kexp) return;
    int m = (int)(i / Kexp), k = (int)(i - (long long)m * Kexp);
    __nv_bfloat16 o;
    if (k >= 4 * K) o = __float2bfloat16(0.f);
    else {
        int t = k / K, c = k - t * K;
        float v = X[(size_t)m * K + c];
        __nv_bfloat16 hi = __float2bfloat16(v);
        o = (t >= 2) ? __float2bfloat16(v - __bfloat162float(hi)) : hi;
    }
    Ae[i] = o;
}

// B-form of X: [hi|lo|hi|lo], zero-padded to Kexp
__global__ void expand_gb(const float* __restrict__ X, __nv_bfloat16* __restrict__ Be,
                          int K, int Kexp) {
    long long i = (long long)blockIdx.x * 256 + threadIdx.x;
    if (i >= (long long)NB * Kexp) return;
    int m = (int)(i / Kexp), k = (int)(i - (long long)m * Kexp);
    __nv_bfloat16 o;
    if (k >= 4 * K) o = __float2bfloat16(0.f);
    else {
        int t = k / K, c = k - t * K;
        float v = X[(size_t)m * K + c];
        __nv_bfloat16 hi = __float2bfloat16(v);
        o = (t & 1) ? __float2bfloat16(v - __bfloat162float(hi)) : hi;
    }
    Be[i] = o;
}

// B-form of Wc^T: [hi|lo|hi|lo], rows n in [0,2cout)
__global__ void expand_wc(const float* __restrict__ W, __nv_bfloat16* __restrict__ Be,
                          int cin, int cout, int Kexp) {
    int i = blockIdx.x * 256 + threadIdx.x;
    int tot = 2 * cout * Kexp;
    if (i >= tot) return;
    int n = i / Kexp, k = i - n * Kexp;
    __nv_bfloat16 o;
    if (k >= 4 * cin) o = __float2bfloat16(0.f);
    else {
        int t = k / cin, c = k - t * cin;
        float v;
        if (n < cout) v = W[c * cout + n];
        else { int dd = n - cout; v = W[(cin + c) * cout + dd] - W[c * cout + dd]; }
        __nv_bfloat16 hi = __float2bfloat16(v);
        o = (t & 1) ? __float2bfloat16(v - __bfloat162float(hi)) : hi;
    }
    Be[i] = o;
}

__global__ void expand_cat(const float* __restrict__ X1, const float* __restrict__ X2,
                           const float* __restrict__ X3, const float* __restrict__ X4,
                           __nv_bfloat16* __restrict__ Ae) {
    long long i = (long long)blockIdx.x * 256 + threadIdx.x;   // NB*1536
    int m = (int)(i / 1536);
    int k = (int)(i - (long long)m * 1536);
    int t = k >> 9, k0 = k & 511;
    float v;
    if (k0 < 64)       v = X1[(size_t)m * 64 + k0];
    else if (k0 < 128) v = X2[(size_t)m * 64 + k0 - 64];
    else if (k0 < 256) v = X3[(size_t)m * 128 + k0 - 128];
    else               v = X4[(size_t)m * 256 + k0 - 256];
    __nv_bfloat16 hi = __float2bfloat16(v);
    Ae[i] = (t == 2) ? __float2bfloat16(v - __bfloat162float(hi)) : hi;
}

__global__ void expand_w5(const float* __restrict__ W, __nv_bfloat16* __restrict__ Be) {
    long long i = (long long)blockIdx.x * 256 + threadIdx.x;   // 1024*1536
    int n = (int)(i / 1536);
    int k = (int)(i - (long long)n * 1536);
    int t = k >> 9, k0 = k & 511;
    float v = W[(size_t)k0 * 1024 + n];
    __nv_bfloat16 hi = __float2bfloat16(v);
    Be[i] = (t == 1) ? __float2bfloat16(v - __bfloat162float(hi)) : hi;
}

// ---------------- squared norms ----------------------------------------------
__global__ void xx_kernel(const float* __restrict__ X, float* __restrict__ xx, int C) {
    int gw = (blockIdx.x * blockDim.x + threadIdx.x) >> 5;
    int lane = threadIdx.x & 31;
    if (gw >= NB) return;
    const float* row = X + (size_t)gw * C;
    float s = 0.f;
    for (int c = lane; c < C; c += 32) { float v = row[c]; s += v * v; }
    #pragma unroll
    for (int o = 16; o > 0; o >>= 1) s += __shfl_xor_sync(0xFFFFFFFFu, s, o);
    if (lane == 0) xx[gw] = s;
}

// ---------------- top-20: threshold select (redux tournament + compaction) ---
__device__ __forceinline__ uint32_t fmono(float f) {
    uint32_t bts = __float_as_uint(f);
    return (bts & 0x80000000u) ? ~bts : (bts | 0x80000000u);
}
#define CASD(x, y) { uint32_t hi = max(u[x], u[y]); uint32_t lo = min(u[x], u[y]); u[x] = hi; u[y] = lo; }
#define CASW(x, y) { uint32_t hi = max(w[x], w[y]); uint32_t lo = min(w[x], w[y]); w[x] = hi; w[y] = lo; }

__global__ void __launch_bounds__(256) topk_kernel(const float* __restrict__ negd,
                                                   int* __restrict__ idxout) {
    __shared__ uint32_t swv[160];
    __shared__ uint32_t s_T;
    __shared__ int s_ngt, s_neq;
    __shared__ int s_eq[64];
    int row = blockIdx.x, b = row >> 11, tid = threadIdx.x;
    int lane = tid & 31, wid = tid >> 5;
    const float* Grow = negd + (size_t)row * NPTS;
    float v[8]; uint32_t u[8];
    #pragma unroll
    for (int i = 0; i < 8; i++) { v[i] = __ldg(&Grow[tid + (i << 8)]); u[i] = fmono(v[i]); }
    CASD(0,1) CASD(2,3) CASD(4,5) CASD(6,7)
    CASD(0,2) CASD(1,3) CASD(4,6) CASD(5,7)
    CASD(1,2) CASD(5,6)
    CASD(0,4) CASD(1,5) CASD(2,6) CASD(3,7)
    CASD(2,4) CASD(3,5)
    CASD(1,2) CASD(3,4) CASD(5,6)
    #pragma unroll 1
    for (int r = 0; r < KNN; r++) {
        uint32_t m;
        asm volatile("redux.sync.max.u32 %0, %1, 0xffffffff;" : "=r"(m) : "r"(u[0]));
        uint32_t bal = __ballot_sync(0xffffffffu, u[0] == m);
        if (lane == (int)(__ffs(bal) - 1)) {
            #pragma unroll
            for (int i = 0; i < 7; i++) u[i] = u[i + 1];
            u[7] = 0;
        }
        if (lane == 0) swv[wid * KNN + r] = m;
    }
    if (tid == 0) { s_ngt = 0; s_neq = 0; }
    __syncthreads();
    if (wid == 0) {
        uint32_t w[5];
        #pragma unroll
        for (int t = 0; t < 5; t++) w[t] = swv[lane + (t << 5)];
        CASW(0,1) CASW(3,4) CASW(2,4) CASW(2,3) CASW(1,4)
        CASW(0,3) CASW(0,2) CASW(1,3) CASW(1,2)
        uint32_t T = 0;
        #pragma unroll 1
        for (int r = 0; r < KNN; r++) {
            asm volatile("redux.sync.max.u32 %0, %1, 0xffffffff;" : "=r"(T) : "r"(w[0]));
            uint32_t bal = __ballot_sync(0xffffffffu, w[0] == T);
            if (lane == (int)(__ffs(bal) - 1)) {
                w[0] = w[1]; w[1] = w[2]; w[2] = w[3]; w[3] = w[4]; w[4] = 0;
            }
        }
        if (lane == 0) s_T = T;
    }
    __syncthreads();
    uint32_t T = s_T;
    int* outp = idxout + row * KNN;
    #pragma unroll
    for (int i = 0; i < 8; i++) {
        uint32_t ui = fmono(v[i]);
        if (ui > T) {
            int p = atomicAdd(&s_ngt, 1);
            outp[p] = (b << 11) + tid + (i << 8);
        } else if (ui == T) {
            int p = atomicAdd(&s_neq, 1);
            if (p < 64) s_eq[p] = tid + (i << 8);
        }
    }
    __syncthreads();
    if (tid == 0) {
        int ngt = s_ngt;
        int neq = s_neq < 64 ? s_neq : 64;
        int need = KNN - ngt;
        for (int t = 0; t < need; t++) {
            int bvv = 0x7fffffff, bi = 0;
            for (int q = 0; q < neq; q++)
                if (s_eq[q] < bvv) { bvv = s_eq[q]; bi = q; }
            s_eq[bi] = 0x7fffffff;
            outp[ngt + t] = (b << 11) + bvv;
        }
    }
}

// ---------------- gather + max/min + epilogue (float4) -----------------------
__global__ void gathermax4_kernel(const float* __restrict__ PC,
                                  const int* __restrict__ idx,
                                  const float* __restrict__ g,
                                  const float* __restrict__ bias,
                                  float* __restrict__ Xout, int cl) {
    int cout = 1 << cl;
    int i = blockIdx.x * 256 + threadIdx.x;      // over NB*cout/4
    int n = i >> (cl - 2);
    int d = (i & ((cout >> 2) - 1)) << 2;
    int ld = cout << 1;
    const int* ip = idx + n * KNN;
    float4 mx = make_float4(-FLT_MAX, -FLT_MAX, -FLT_MAX, -FLT_MAX);
    float4 mn = make_float4(FLT_MAX, FLT_MAX, FLT_MAX, FLT_MAX);
    #pragma unroll
    for (int k = 0; k < KNN; k++) {
        float4 v = *(const float4*)&PC[(size_t)__ldg(&ip[k]) * ld + d];
        mx.x = fmaxf(mx.x, v.x); mn.x = fminf(mn.x, v.x);
        mx.y = fmaxf(mx.y, v.y); mn.y = fminf(mn.y, v.y);
        mx.z = fmaxf(mx.z, v.z); mn.z = fminf(mn.z, v.z);
        mx.w = fmaxf(mx.w, v.w); mn.w = fminf(mn.w, v.w);
    }
    float4 Cc = *(const float4*)&PC[(size_t)n * ld + cout + d];
    float4 gd = *(const float4*)&g[d];
    float4 bd = *(const float4*)&bias[d];
    float4 o;
    float z;
    z = (gd.x >= 0.f ? mx.x : mn.x) + Cc.x; z = fmaf(gd.x, z, bd.x); o.x = z >= 0.f ? z : NEG_SLOPE * z;
    z = (gd.y >= 0.f ? mx.y : mn.y) + Cc.y; z = fmaf(gd.y, z, bd.y); o.y = z >= 0.f ? z : NEG_SLOPE * z;
    z = (gd.z >= 0.f ? mx.z : mn.z) + Cc.z; z = fmaf(gd.z, z, bd.z); o.z = z >= 0.f ? z : NEG_SLOPE * z;
    z = (gd.w >= 0.f ? mx.w : mn.w) + Cc.w; z = fmaf(gd.w, z, bd.w); o.w = z >= 0.f ? z : NEG_SLOPE * z;
    *(float4*)&Xout[(size_t)n * cout + d] = o;
}

// ---------------- host launch -------------------------------------------------
extern "C" void kernel_launch(void* const* d_in, const int* in_sizes, int n_in,
                              void* d_out, int out_size) {
    (void)in_sizes; (void)n_in; (void)out_size;
    const float* pts = (const float*)d_in[0];
    const float* W[5]; const float* gg[5]; const float* bb[5];
    for (int i = 0; i < 5; i++) {
        W[i]  = (const float*)d_in[1 + 3 * i];
        gg[i] = (const float*)d_in[2 + 3 * i];
        bb[i] = (const float*)d_in[3 + 3 * i];
    }
    float* out = (float*)d_out;

    float *X1, *X2, *X3, *X4, *PC, *G, *XX; int* IDX;
    __nv_bfloat16 *XA, *XB, *WCE, *CE, *WE;
    cudaGetSymbolAddress((void**)&X1, g_X1);
    cudaGetSymbolAddress((void**)&X2, g_X2);
    cudaGetSymbolAddress((void**)&X3, g_X3);
    cudaGetSymbolAddress((void**)&X4, g_X4);
    cudaGetSymbolAddress((void**)&PC, g_PC);
    cudaGetSymbolAddress((void**)&G,  g_G);
    cudaGetSymbolAddress((void**)&XX, g_xx);
    cudaGetSymbolAddress((void**)&IDX, g_idx);
    cudaGetSymbolAddress((void**)&XA, g_XexpA);
    cudaGetSymbolAddress((void**)&XB, g_XexpB);
    cudaGetSymbolAddress((void**)&WCE, g_WcExp);
    cudaGetSymbolAddress((void**)&CE, g_CATexp);
    cudaGetSymbolAddress((void**)&WE, g_W5exp);

    cudaFuncSetAttribute(gram_hmma, cudaFuncAttributeMaxDynamicSharedMemorySize, GR_SMEM);
    cudaFuncSetAttribute(w5_hmma,   cudaFuncAttributeMaxDynamicSharedMemorySize, W5_SMEM);
    cudaFuncSetAttribute(pc_hmma,   cudaFuncAttributeMaxDynamicSharedMemorySize, W5_SMEM);

    struct L { const float* Xin; int cin, cout, cl, kexp; float* Xout; };
    L layers[4] = {
        { pts, 3,   64,  6, 64,  X1 },   // 4*3=12 -> pad 64
        { X1,  64,  64,  6, 256, X2 },   // 4*64 = 256
        { X2,  64,  128, 7, 256, X3 },
        { X3,  128, 256, 8, 512, X4 },   // 4*128 = 512
    };
    for (int li = 0; li < 4; li++) {
        const L& l = layers[li];
        xx_kernel<<<NB / 8, 256>>>(l.Xin, XX, l.cin);
        long long etot = (long long)NB * l.kexp;
        expand_px<<<(unsigned)((etot + 255) / 256), 256>>>(l.Xin, XA, l.cin, l.kexp);
        expand_gb<<<(unsigned)((etot + 255) / 256), 256>>>(l.Xin, XB, l.cin, l.kexp);
        gram_hmma<<<dim3(136, 1, BATCH), 256, GR_SMEM>>>(XA, XB, XX, G, l.kexp);
        topk_kernel<<<NB, 256>>>(G, IDX);
        int N2 = 2 * l.cout;
        int wtot = N2 * l.kexp;
        expand_wc<<<(wtot + 255) / 256, 256>>>(W[li], WCE, l.cin, l.cout, l.kexp);
        pc_hmma<<<dim3(N2 / 128, NB / 128), 256, W5_SMEM>>>(XA, WCE, PC, N2, l.kexp);
        gathermax4_kernel<<<(NB * l.cout / 4) / 256, 256>>>(PC, IDX, gg[li], bb[li], l.Xout, l.cl);
    }
    expand_cat<<<(unsigned)(((long long)NB * 1536 + 255) / 256), 256>>>(X1, X2, X3, X4, CE);
    expand_w5<<<(1024 * 1536) / 256, 256>>>(W[4], WE);
    w5_hmma<<<dim3(1024 / 128, NB / 128), 256, W5_SMEM>>>(CE, WE, gg[4], bb[4], out);
}

// round 16
// speedup vs baseline: 1.1301x; 1.1301x over previous
#include <cuda_runtime.h>
#include <cuda_bf16.h>
#include <float.h>
#include <stdint.h>

#define NB    16384
#define NPTS  2048
#define BATCH 8
#define KNN   20
#define NEG_SLOPE 0.2f

// ---------------- scratch (device globals) ----------------------------------
__device__ float g_X1[NB * 64];
__device__ float g_X2[NB * 64];
__device__ float g_X3[NB * 128];
__device__ float g_X4[NB * 256];
__device__ float g_PC[NB * 512];
__device__ float g_G[(size_t)BATCH * NPTS * NPTS];   // holds negd
__device__ float g_xx[NB];
__device__ int   g_idx[NB * KNN];
__device__ float g_Wcomb[128 * 512];
__device__ __nv_bfloat16 g_XexpA[(size_t)NB * 384];  // 3-term A-form (Gram)
__device__ __nv_bfloat16 g_XexpB[(size_t)NB * 384];  // 3-term B-form (Gram)
__device__ __nv_bfloat16 g_CATexp[(size_t)NB * 1536];
__device__ __nv_bfloat16 g_W5exp[(size_t)1024 * 1536];

// ======================= warp-MMA helpers (plain PTX, sm_80+) ================
__device__ __forceinline__ uint32_t smem_u32(const void* p) {
    uint32_t a;
    asm("{ .reg .u64 t; cvta.to.shared.u64 t, %1; cvt.u32.u64 %0, t; }"
        : "=r"(a) : "l"(p));
    return a;
}

#define SWZ(o) ((o) ^ (((o) >> 3) & 0x70))

#define LDSM4(r, a) \
    asm volatile("ldmatrix.sync.aligned.m8n8.x4.shared.b16 {%0,%1,%2,%3}, [%4];" \
        : "=r"((r)[0]), "=r"((r)[1]), "=r"((r)[2]), "=r"((r)[3]) : "r"(a))

#define MMA16816(d, a, b0, b1) \
    asm volatile("mma.sync.aligned.m16n8k16.row.col.f32.bf16.bf16.f32 " \
        "{%0,%1,%2,%3},{%4,%5,%6,%7},{%8,%9},{%0,%1,%2,%3};" \
        : "+f"((d)[0]), "+f"((d)[1]), "+f"((d)[2]), "+f"((d)[3]) \
        : "r"((a)[0]), "r"((a)[1]), "r"((a)[2]), "r"((a)[3]), "r"(b0), "r"(b1))

#define CP_ASYNC16(dst, src) \
    asm volatile("cp.async.cg.shared.global [%0], [%1], 16;" :: "r"(dst), "l"(src))
#define CP_COMMIT() asm volatile("cp.async.commit_group;")
#define CP_WAIT0()  asm volatile("cp.async.wait_group 0;")

#define STAGE_B 16384                      // 128 rows x 128 bytes
#define W5_SMEM (4 * STAGE_B + 128)        // 2 stages x 2 operands
#define TILE_PITCH 133
#define GR_SMEM (128 * TILE_PITCH * 4 + 256)  // transpose tile dominates

// mainloop: acc += A(128 x 64*kc) * B(128 x 64*kc)^T, both row-major bf16.
// cp.async double-buffer (no register prefetch -> lower reg pressure, 2 CTA/SM)
__device__ __forceinline__ void hmma_loop(char* sm, const char* Ag, const char* Bg,
                                          size_t strA, size_t strB, int kchunks,
                                          int tid, float acc[2][8][4]) {
    char* sA = sm;
    char* sB = sm + 2 * STAGE_B;
    int lane = tid & 31, wid = tid >> 5;
    int wm = wid & 3, wn = wid >> 2;
    int r = tid >> 3, cbyte = (tid & 7) * 16;
    uint32_t sA32 = smem_u32(sA), sB32 = smem_u32(sB);
    // preload stage 0
    #pragma unroll
    for (int i = 0; i < 4; i++) {
        int row = r + 32 * i;
        uint32_t o = SWZ((uint32_t)(row * 128 + cbyte));
        CP_ASYNC16(sA32 + o, Ag + (size_t)row * strA + cbyte);
        CP_ASYNC16(sB32 + o, Bg + (size_t)row * strB + cbyte);
    }
    CP_COMMIT();
    CP_WAIT0();
    __syncthreads();
    int buf = 0;
    for (int c = 0; c < kchunks; c++) {
        if (c + 1 < kchunks) {
            const char* An = Ag + (size_t)(c + 1) * 128;
            const char* Bn = Bg + (size_t)(c + 1) * 128;
            uint32_t dA = sA32 + (buf ^ 1) * STAGE_B;
            uint32_t dB = sB32 + (buf ^ 1) * STAGE_B;
            #pragma unroll
            for (int i = 0; i < 4; i++) {
                int row = r + 32 * i;
                uint32_t o = SWZ((uint32_t)(row * 128 + cbyte));
                CP_ASYNC16(dA + o, An + (size_t)row * strA + cbyte);
                CP_ASYNC16(dB + o, Bn + (size_t)row * strB + cbyte);
            }
            CP_COMMIT();
        }
        uint32_t aB = sA32 + buf * STAGE_B, bB = sB32 + buf * STAGE_B;
        #pragma unroll
        for (int ks = 0; ks < 4; ks++) {
            uint32_t a[2][4], b[4][4];
            #pragma unroll
            for (int mi = 0; mi < 2; mi++) {
                int row = wm * 32 + mi * 16 + (lane & 15);
                int off = row * 128 + ks * 32 + ((lane >> 4) << 4);
                LDSM4(a[mi], aB + SWZ(off));
            }
            #pragma unroll
            for (int np = 0; np < 4; np++) {
                int row = wn * 64 + np * 16 + ((lane >> 4) << 3) + (lane & 7);
                int off = row * 128 + ks * 32 + (((lane >> 3) & 1) << 4);
                LDSM4(b[np], bB + SWZ(off));
            }
            #pragma unroll
            for (int mi = 0; mi < 2; mi++)
                #pragma unroll
                for (int nj = 0; nj < 8; nj++)
                    MMA16816(acc[mi][nj], a[mi], b[nj >> 1][(nj & 1) * 2], b[nj >> 1][(nj & 1) * 2 + 1]);
        }
        if (c + 1 < kchunks) {
            CP_WAIT0();
            __syncthreads();
            buf ^= 1;
        }
    }
}

// --------- Gram (triangular blocks): negd = 2*X@X^T - xx_m - xx_n ------------
__global__ void __launch_bounds__(256, 2) gram_hmma(const __nv_bfloat16* __restrict__ Ae,
                                                    const __nv_bfloat16* __restrict__ Be,
                                                    const float* __restrict__ xx,
                                                    float* __restrict__ negd, int Kexp) {
    extern __shared__ char dsm[];
    uint32_t sb = smem_u32(dsm);
    char* sm = dsm + (((sb + 127) & ~127u) - sb);
    int tid = threadIdx.x, lane = tid & 31, wid = tid >> 5;
    int wm = wid & 3, wn = wid >> 2;
    int b = blockIdx.z;
    int rem = blockIdx.x, ti = 0;
    while (rem >= 16 - ti) { rem -= 16 - ti; ti++; }
    int tj = ti + rem;
    int m0 = ti * 128, n0 = tj * 128;

    float acc[2][8][4] = {};
    size_t str = (size_t)Kexp * 2;
    hmma_loop(sm, (const char*)(Ae + (size_t)(b * NPTS + m0) * Kexp),
                  (const char*)(Be + (size_t)(b * NPTS + n0) * Kexp),
              str, str, Kexp >> 6, tid, acc);

    const float* xxb = xx + b * NPTS;
    float* nd = negd + ((size_t)b << 22);
    float (*tile)[TILE_PITCH] = (float(*)[TILE_PITCH])sm;

    if (ti != tj) __syncthreads();

    #pragma unroll
    for (int mi = 0; mi < 2; mi++) {
        int lm0 = wm * 32 + mi * 16 + (lane >> 2);
        int rowa = m0 + lm0;
        float xm0 = __ldg(&xxb[rowa]), xm1 = __ldg(&xxb[rowa + 8]);
        #pragma unroll
        for (int nj = 0; nj < 8; nj++) {
            int ln = wn * 64 + nj * 8 + (lane & 3) * 2;
            int col = n0 + ln;
            float xn0 = __ldg(&xxb[col]), xn1 = __ldg(&xxb[col + 1]);
            float v00 = 2.f * acc[mi][nj][0] - xm0 - xn0;
            float v01 = 2.f * acc[mi][nj][1] - xm0 - xn1;
            float v10 = 2.f * acc[mi][nj][2] - xm1 - xn0;
            float v11 = 2.f * acc[mi][nj][3] - xm1 - xn1;
            *(float2*)&nd[(size_t)rowa * NPTS + col]       = make_float2(v00, v01);
            *(float2*)&nd[(size_t)(rowa + 8) * NPTS + col] = make_float2(v10, v11);
            if (ti != tj) {
                tile[lm0][ln]         = v00;
                tile[lm0][ln + 1]     = v01;
                tile[lm0 + 8][ln]     = v10;
                tile[lm0 + 8][ln + 1] = v11;
            }
        }
    }
    if (ti != tj) {
        __syncthreads();
        int nn = tid >> 1;
        int mmBase = (tid & 1) * 64;
        size_t gbase = (size_t)(n0 + nn) * NPTS + m0 + mmBase;
        #pragma unroll
        for (int k4 = 0; k4 < 16; k4++) {
            int mm = mmBase + k4 * 4;
            float4 w = make_float4(tile[mm][nn], tile[mm + 1][nn],
                                   tile[mm + 2][nn], tile[mm + 3][nn]);
            *(float4*)&nd[gbase + k4 * 4] = w;
        }
    }
}

// --------- W5: out = lrelu(cat@W5 * g + b), transposed store -----------------
__global__ void __launch_bounds__(256, 2) w5_hmma(const __nv_bfloat16* __restrict__ Ae,
                                                  const __nv_bfloat16* __restrict__ Be,
                                                  const float* __restrict__ g,
                                                  const float* __restrict__ bias,
                                                  float* __restrict__ out) {
    extern __shared__ char dsm[];
    uint32_t sb = smem_u32(dsm);
    char* sm = dsm + (((sb + 127) & ~127u) - sb);
    int tid = threadIdx.x, lane = tid & 31, wid = tid >> 5;
    int wm = wid & 3, wn = wid >> 2;
    int m0 = blockIdx.y * 128, n0 = blockIdx.x * 128;

    float acc[2][8][4] = {};
    hmma_loop(sm, (const char*)(Ae + (size_t)m0 * 1536),
                  (const char*)(Be + (size_t)n0 * 1536),
              3072, 3072, 24, tid, acc);

    #pragma unroll
    for (int mi = 0; mi < 2; mi++) {
        int m = m0 + wm * 32 + mi * 16 + (lane >> 2);
        #pragma unroll
        for (int half = 0; half < 2; half++) {
            int mr = m + half * 8;
            int bidx = mr >> 11, npt = mr & 2047;
            size_t obase = ((size_t)bidx << 10) * NPTS + npt;
            #pragma unroll
            for (int nj = 0; nj < 8; nj++) {
                int col = n0 + wn * 64 + nj * 8 + (lane & 3) * 2;
                float g0 = __ldg(&g[col]), g1 = __ldg(&g[col + 1]);
                float b0 = __ldg(&bias[col]), b1 = __ldg(&bias[col + 1]);
                float z0 = fmaf(acc[mi][nj][half * 2],     g0, b0);
                float z1 = fmaf(acc[mi][nj][half * 2 + 1], g1, b1);
                out[obase + (size_t)col * NPTS]       = z0 >= 0.f ? z0 : NEG_SLOPE * z0;
                out[obase + (size_t)(col + 1) * NPTS] = z1 >= 0.f ? z1 : NEG_SLOPE * z1;
            }
        }
    }
}

// ---------------- bf16x3 expansion kernels (Gram only) -----------------------
__global__ void expand_gram(const float* __restrict__ X, __nv_bfloat16* __restrict__ Ae,
                            __nv_bfloat16* __restrict__ Be, int K, int Kexp) {
    long long i = (long long)blockIdx.x * 256 + threadIdx.x;
    if (i >= (long long)NB * Kexp) return;
    int m = (int)(i / Kexp), k = (int)(i - (long long)m * Kexp);
    int t = (k < K) ? 0 : (k < 2 * K) ? 1 : (k < 3 * K) ? 2 : 3;
    __nv_bfloat16 av, bv;
    if (t == 3) { av = __float2bfloat16(0.f); bv = av; }
    else {
        float v = X[(size_t)m * K + (k - t * K)];
        __nv_bfloat16 hi = __float2bfloat16(v);
        __nv_bfloat16 lo = __float2bfloat16(v - __bfloat162float(hi));
        av = (t == 2) ? lo : hi;
        bv = (t == 1) ? lo : hi;
    }
    Ae[i] = av; Be[i] = bv;
}

__global__ void expand_cat(const float* __restrict__ X1, const float* __restrict__ X2,
                           const float* __restrict__ X3, const float* __restrict__ X4,
                           __nv_bfloat16* __restrict__ Ae) {
    long long i = (long long)blockIdx.x * 256 + threadIdx.x;   // NB*1536
    int m = (int)(i / 1536);
    int k = (int)(i - (long long)m * 1536);
    int t = k >> 9, k0 = k & 511;
    float v;
    if (k0 < 64)       v = X1[(size_t)m * 64 + k0];
    else if (k0 < 128) v = X2[(size_t)m * 64 + k0 - 64];
    else if (k0 < 256) v = X3[(size_t)m * 128 + k0 - 128];
    else               v = X4[(size_t)m * 256 + k0 - 256];
    __nv_bfloat16 hi = __float2bfloat16(v);
    Ae[i] = (t == 2) ? __float2bfloat16(v - __bfloat162float(hi)) : hi;
}

__global__ void expand_w5(const float* __restrict__ W, __nv_bfloat16* __restrict__ Be) {
    long long i = (long long)blockIdx.x * 256 + threadIdx.x;   // 1024*1536
    int n = (int)(i / 1536);
    int k = (int)(i - (long long)n * 1536);
    int t = k >> 9, k0 = k & 511;
    float v = W[(size_t)k0 * 1024 + n];
    __nv_bfloat16 hi = __float2bfloat16(v);
    Be[i] = (t == 1) ? __float2bfloat16(v - __bfloat162float(hi)) : hi;
}

// ---------------- squared norms ----------------------------------------------
__global__ void xx_kernel(const float* __restrict__ X, float* __restrict__ xx, int C) {
    int gw = (blockIdx.x * blockDim.x + threadIdx.x) >> 5;
    int lane = threadIdx.x & 31;
    if (gw >= NB) return;
    const float* row = X + (size_t)gw * C;
    float s = 0.f;
    for (int c = lane; c < C; c += 32) { float v = row[c]; s += v * v; }
    #pragma unroll
    for (int o = 16; o > 0; o >>= 1) s += __shfl_xor_sync(0xFFFFFFFFu, s, o);
    if (lane == 0) xx[gw] = s;
}

// ---------------- PC: fp32 SIMT 64x64 tiles, ascending-k (bit-exact) ---------
__global__ void __launch_bounds__(256) gemm_nn64(const float* __restrict__ A,
                                                 const float* __restrict__ B,
                                                 float* __restrict__ Cout,
                                                 int N, int Kdim) {
    __shared__ float As[2][8][68];   // [k][m]
    __shared__ float Bs[2][8][68];   // [k][n]
    int tid = threadIdx.x;
    int m0 = blockIdx.y * 64, n0 = blockIdx.x * 64;
    int tm = tid >> 4, tn = tid & 15;
    int la_m = tid >> 3, la_k = tid & 7;      // A: 64x8, 2 rows/thread
    int lb_k = tid >> 6, lb_n = tid & 63;     // B: 8x64, 2 k/thread
    float acc[4][4] = {};
    float ra[2], rb[2];
    int kIters = (Kdim + 7) / 8;
    #pragma unroll
    for (int j = 0; j < 2; j++) {
        ra[j] = (la_k < Kdim) ? A[(size_t)(m0 + la_m + 32 * j) * Kdim + la_k] : 0.f;
        int kb = lb_k + 4 * j;
        rb[j] = (kb < Kdim) ? B[(size_t)kb * N + n0 + lb_n] : 0.f;
    }
    #pragma unroll
    for (int j = 0; j < 2; j++) {
        As[0][la_k][la_m + 32 * j] = ra[j];
        Bs[0][lb_k + 4 * j][lb_n] = rb[j];
    }
    __syncthreads();
    int buf = 0;
    for (int it = 0; it < kIters; ++it) {
        if (it + 1 < kIters) {
            int k0n = (it + 1) * 8;
            #pragma unroll
            for (int j = 0; j < 2; j++) {
                int ka = k0n + la_k;
                ra[j] = (ka < Kdim) ? A[(size_t)(m0 + la_m + 32 * j) * Kdim + ka] : 0.f;
                int kb = k0n + lb_k + 4 * j;
                rb[j] = (kb < Kdim) ? B[(size_t)kb * N + n0 + lb_n] : 0.f;
            }
        }
        #pragma unroll
        for (int k = 0; k < 8; k++) {
            float4 a4 = *(const float4*)&As[buf][k][tm * 4];
            float4 b4 = *(const float4*)&Bs[buf][k][tn * 4];
            float av[4] = {a4.x, a4.y, a4.z, a4.w};
            float bv[4] = {b4.x, b4.y, b4.z, b4.w};
            #pragma unroll
            for (int ii = 0; ii < 4; ii++)
                #pragma unroll
                for (int jj = 0; jj < 4; jj++)
                    acc[ii][jj] = fmaf(av[ii], bv[jj], acc[ii][jj]);
        }
        if (it + 1 < kIters) {
            #pragma unroll
            for (int j = 0; j < 2; j++) {
                As[buf ^ 1][la_k][la_m + 32 * j] = ra[j];
                Bs[buf ^ 1][lb_k + 4 * j][lb_n] = rb[j];
            }
        }
        __syncthreads();
        buf ^= 1;
    }
    #pragma unroll
    for (int ii = 0; ii < 4; ii++) {
        *(float4*)&Cout[(size_t)(m0 + tm * 4 + ii) * N + n0 + tn * 4] =
            make_float4(acc[ii][0], acc[ii][1], acc[ii][2], acc[ii][3]);
    }
}

// ---------------- top-20: threshold select (redux tournament + compaction) ---
__device__ __forceinline__ uint32_t fmono(float f) {
    uint32_t bts = __float_as_uint(f);
    return (bts & 0x80000000u) ? ~bts : (bts | 0x80000000u);
}
#define CASD(x, y) { uint32_t hi = max(u[x], u[y]); uint32_t lo = min(u[x], u[y]); u[x] = hi; u[y] = lo; }
#define CASW(x, y) { uint32_t hi = max(w[x], w[y]); uint32_t lo = min(w[x], w[y]); w[x] = hi; w[y] = lo; }

__global__ void __launch_bounds__(256) topk_kernel(const float* __restrict__ negd,
                                                   int* __restrict__ idxout) {
    __shared__ uint32_t swv[160];
    __shared__ uint32_t s_T;
    __shared__ int s_ngt, s_neq;
    __shared__ int s_eq[64];
    int row = blockIdx.x, b = row >> 11, tid = threadIdx.x;
    int lane = tid & 31, wid = tid >> 5;
    const float* Grow = negd + (size_t)row * NPTS;
    float v[8]; uint32_t u[8];
    #pragma unroll
    for (int i = 0; i < 8; i++) { v[i] = __ldg(&Grow[tid + (i << 8)]); u[i] = fmono(v[i]); }
    CASD(0,1) CASD(2,3) CASD(4,5) CASD(6,7)
    CASD(0,2) CASD(1,3) CASD(4,6) CASD(5,7)
    CASD(1,2) CASD(5,6)
    CASD(0,4) CASD(1,5) CASD(2,6) CASD(3,7)
    CASD(2,4) CASD(3,5)
    CASD(1,2) CASD(3,4) CASD(5,6)
    #pragma unroll 1
    for (int r = 0; r < KNN; r++) {
        uint32_t m;
        asm volatile("redux.sync.max.u32 %0, %1, 0xffffffff;" : "=r"(m) : "r"(u[0]));
        uint32_t bal = __ballot_sync(0xffffffffu, u[0] == m);
        if (lane == (int)(__ffs(bal) - 1)) {
            #pragma unroll
            for (int i = 0; i < 7; i++) u[i] = u[i + 1];
            u[7] = 0;
        }
        if (lane == 0) swv[wid * KNN + r] = m;
    }
    if (tid == 0) { s_ngt = 0; s_neq = 0; }
    __syncthreads();
    if (wid == 0) {
        uint32_t w[5];
        #pragma unroll
        for (int t = 0; t < 5; t++) w[t] = swv[lane + (t << 5)];
        CASW(0,1) CASW(3,4) CASW(2,4) CASW(2,3) CASW(1,4)
        CASW(0,3) CASW(0,2) CASW(1,3) CASW(1,2)
        uint32_t T = 0;
        #pragma unroll 1
        for (int r = 0; r < KNN; r++) {
            asm volatile("redux.sync.max.u32 %0, %1, 0xffffffff;" : "=r"(T) : "r"(w[0]));
            uint32_t bal = __ballot_sync(0xffffffffu, w[0] == T);
            if (lane == (int)(__ffs(bal) - 1)) {
                w[0] = w[1]; w[1] = w[2]; w[2] = w[3]; w[3] = w[4]; w[4] = 0;
            }
        }
        if (lane == 0) s_T = T;
    }
    __syncthreads();
    uint32_t T = s_T;
    int* outp = idxout + row * KNN;
    #pragma unroll
    for (int i = 0; i < 8; i++) {
        uint32_t ui = fmono(v[i]);
        if (ui > T) {
            int p = atomicAdd(&s_ngt, 1);
            outp[p] = (b << 11) + tid + (i << 8);
        } else if (ui == T) {
            int p = atomicAdd(&s_neq, 1);
            if (p < 64) s_eq[p] = tid + (i << 8);
        }
    }
    __syncthreads();
    if (tid == 0) {
        int ngt = s_ngt;
        int neq = s_neq < 64 ? s_neq : 64;
        int need = KNN - ngt;
        for (int t = 0; t < need; t++) {
            int bvv = 0x7fffffff, bi = 0;
            for (int q = 0; q < neq; q++)
                if (s_eq[q] < bvv) { bvv = s_eq[q]; bi = q; }
            s_eq[bi] = 0x7fffffff;
            outp[ngt + t] = (b << 11) + bvv;
        }
    }
}

// ---------------- gather + max/min + epilogue (float4) -----------------------
__global__ void gathermax4_kernel(const float* __restrict__ PC,
                                  const int* __restrict__ idx,
                                  const float* __restrict__ g,
                                  const float* __restrict__ bias,
                                  float* __restrict__ Xout, int cl) {
    int cout = 1 << cl;
    int i = blockIdx.x * 256 + threadIdx.x;      // over NB*cout/4
    int n = i >> (cl - 2);
    int d = (i & ((cout >> 2) - 1)) << 2;
    int ld = cout << 1;
    const int* ip = idx + n * KNN;
    float4 mx = make_float4(-FLT_MAX, -FLT_MAX, -FLT_MAX, -FLT_MAX);
    float4 mn = make_float4(FLT_MAX, FLT_MAX, FLT_MAX, FLT_MAX);
    #pragma unroll
    for (int k = 0; k < KNN; k++) {
        float4 v = *(const float4*)&PC[(size_t)__ldg(&ip[k]) * ld + d];
        mx.x = fmaxf(mx.x, v.x); mn.x = fminf(mn.x, v.x);
        mx.y = fmaxf(mx.y, v.y); mn.y = fminf(mn.y, v.y);
        mx.z = fmaxf(mx.z, v.z); mn.z = fminf(mn.z, v.z);
        mx.w = fmaxf(mx.w, v.w); mn.w = fminf(mn.w, v.w);
    }
    float4 Cc = *(const float4*)&PC[(size_t)n * ld + cout + d];
    float4 gd = *(const float4*)&g[d];
    float4 bd = *(const float4*)&bias[d];
    float4 o;
    float z;
    z = (gd.x >= 0.f ? mx.x : mn.x) + Cc.x; z = fmaf(gd.x, z, bd.x); o.x = z >= 0.f ? z : NEG_SLOPE * z;
    z = (gd.y >= 0.f ? mx.y : mn.y) + Cc.y; z = fmaf(gd.y, z, bd.y); o.y = z >= 0.f ? z : NEG_SLOPE * z;
    z = (gd.z >= 0.f ? mx.z : mn.z) + Cc.z; z = fmaf(gd.z, z, bd.z); o.z = z >= 0.f ? z : NEG_SLOPE * z;
    z = (gd.w >= 0.f ? mx.w : mn.w) + Cc.w; z = fmaf(gd.w, z, bd.w); o.w = z >= 0.f ? z : NEG_SLOPE * z;
    *(float4*)&Xout[(size_t)n * cout + d] = o;
}

// ---------------- combined weight: [W_a | W_b - W_a] -------------------------
__global__ void wcomb_kernel(const float* __restrict__ W, float* __restrict__ Wc,
                             int cin, int cout) {
    int i = blockIdx.x * 256 + threadIdx.x;
    int tot = cin * 2 * cout;
    if (i >= tot) return;
    int twoc = 2 * cout;
    int c = i / twoc, j = i - c * twoc;
    float v;
    if (j < cout) v = W[c * cout + j];
    else { int dd = j - cout; v = W[(cin + c) * cout + dd] - W[c * cout + dd]; }
    Wc[i] = v;
}

// ---------------- host launch -------------------------------------------------
extern "C" void kernel_launch(void* const* d_in, const int* in_sizes, int n_in,
                              void* d_out, int out_size) {
    (void)in_sizes; (void)n_in; (void)out_size;
    const float* pts = (const float*)d_in[0];
    const float* W[5]; const float* gg[5]; const float* bb[5];
    for (int i = 0; i < 5; i++) {
        W[i]  = (const float*)d_in[1 + 3 * i];
        gg[i] = (const float*)d_in[2 + 3 * i];
        bb[i] = (const float*)d_in[3 + 3 * i];
    }
    float* out = (float*)d_out;

    float *X1, *X2, *X3, *X4, *PC, *G, *XX, *WC; int* IDX;
    __nv_bfloat16 *XA, *XB, *CE, *WE;
    cudaGetSymbolAddress((void**)&X1, g_X1);
    cudaGetSymbolAddress((void**)&X2, g_X2);
    cudaGetSymbolAddress((void**)&X3, g_X3);
    cudaGetSymbolAddress((void**)&X4, g_X4);
    cudaGetSymbolAddress((void**)&PC, g_PC);
    cudaGetSymbolAddress((void**)&G,  g_G);
    cudaGetSymbolAddress((void**)&XX, g_xx);
    cudaGetSymbolAddress((void**)&WC, g_Wcomb);
    cudaGetSymbolAddress((void**)&IDX, g_idx);
    cudaGetSymbolAddress((void**)&XA, g_XexpA);
    cudaGetSymbolAddress((void**)&XB, g_XexpB);
    cudaGetSymbolAddress((void**)&CE, g_CATexp);
    cudaGetSymbolAddress((void**)&WE, g_W5exp);

    cudaFuncSetAttribute(gram_hmma, cudaFuncAttributeMaxDynamicSharedMemorySize, GR_SMEM);
    cudaFuncSetAttribute(w5_hmma,   cudaFuncAttributeMaxDynamicSharedMemorySize, W5_SMEM);

    struct L { const float* Xin; int cin, cout, cl, kexp; float* Xout; };
    L layers[4] = {
        { pts, 3,   64,  6, 64,  X1 },
        { X1,  64,  64,  6, 192, X2 },
        { X2,  64,  128, 7, 192, X3 },
        { X3,  128, 256, 8, 384, X4 },
    };
    for (int li = 0; li < 4; li++) {
        const L& l = layers[li];
        xx_kernel<<<NB / 8, 256>>>(l.Xin, XX, l.cin);
        long long etot = (long long)NB * l.kexp;
        expand_gram<<<(unsigned)((etot + 255) / 256), 256>>>(l.Xin, XA, XB, l.cin, l.kexp);
        gram_hmma<<<dim3(136, 1, BATCH), 256, GR_SMEM>>>(XA, XB, XX, G, l.kexp);
        topk_kernel<<<NB, 256>>>(G, IDX);
        int N2 = 2 * l.cout;
        int tot = l.cin * N2;
        wcomb_kernel<<<(tot + 255) / 256, 256>>>(W[li], WC, l.cin, l.cout);
        gemm_nn64<<<dim3(N2 / 64, NB / 64), 256>>>(l.Xin, WC, PC, N2, l.cin);
        gathermax4_kernel<<<(NB * l.cout / 4) / 256, 256>>>(PC, IDX, gg[li], bb[li], l.Xout, l.cl);
    }
    expand_cat<<<(unsigned)(((long long)NB * 1536 + 255) / 256), 256>>>(X1, X2, X3, X4, CE);
    expand_w5<<<(1024 * 1536) / 256, 256>>>(W[4], WE);
    w5_hmma<<<dim3(1024 / 128, NB / 128), 256, W5_SMEM>>>(CE, WE, gg[4], bb[4], out);
}

// round 17
// speedup vs baseline: 1.3671x; 1.2097x over previous
#include <cuda_runtime.h>
#include <cuda_bf16.h>
#include <float.h>
#include <stdint.h>

#define NB    16384
#define NPTS  2048
#define BATCH 8
#define KNN   20
#define NEG_SLOPE 0.2f

// ---------------- scratch (device globals) ----------------------------------
__device__ float g_X1[NB * 64];
__device__ float g_X2[NB * 64];
__device__ float g_X3[NB * 128];
__device__ float g_X4[NB * 256];
__device__ float g_PC[NB * 512];
__device__ float g_G[(size_t)BATCH * NPTS * NPTS];   // holds fmono(negd) bits
__device__ float g_xx[NB];
__device__ int   g_idx[NB * KNN];
__device__ float g_Wcomb[128 * 512];
__device__ __nv_bfloat16 g_XexpA[(size_t)NB * 384];  // 3-term A-form (Gram)
__device__ __nv_bfloat16 g_XexpB[(size_t)NB * 384];  // 3-term B-form (Gram)
__device__ __nv_bfloat16 g_CATexp[(size_t)NB * 1536];
__device__ __nv_bfloat16 g_W5exp[(size_t)1024 * 1536];

// ---------------- monotone float->uint encode --------------------------------
__device__ __forceinline__ uint32_t fmono(float f) {
    uint32_t bts = __float_as_uint(f);
    return (bts & 0x80000000u) ? ~bts : (bts | 0x80000000u);
}

// ======================= warp-MMA helpers (plain PTX, sm_80+) ================
__device__ __forceinline__ uint32_t smem_u32(const void* p) {
    uint32_t a;
    asm("{ .reg .u64 t; cvta.to.shared.u64 t, %1; cvt.u32.u64 %0, t; }"
        : "=r"(a) : "l"(p));
    return a;
}

#define SWZ(o) ((o) ^ (((o) >> 3) & 0x70))

#define LDSM4(r, a) \
    asm volatile("ldmatrix.sync.aligned.m8n8.x4.shared.b16 {%0,%1,%2,%3}, [%4];" \
        : "=r"((r)[0]), "=r"((r)[1]), "=r"((r)[2]), "=r"((r)[3]) : "r"(a))

#define MMA16816(d, a, b0, b1) \
    asm volatile("mma.sync.aligned.m16n8k16.row.col.f32.bf16.bf16.f32 " \
        "{%0,%1,%2,%3},{%4,%5,%6,%7},{%8,%9},{%0,%1,%2,%3};" \
        : "+f"((d)[0]), "+f"((d)[1]), "+f"((d)[2]), "+f"((d)[3]) \
        : "r"((a)[0]), "r"((a)[1]), "r"((a)[2]), "r"((a)[3]), "r"(b0), "r"(b1))

#define CP_ASYNC16(dst, src) \
    asm volatile("cp.async.cg.shared.global [%0], [%1], 16;" :: "r"(dst), "l"(src))
#define CP_COMMIT() asm volatile("cp.async.commit_group;")
#define CP_WAIT0()  asm volatile("cp.async.wait_group 0;")

#define REDUX_MAX(out, in) \
    asm volatile("redux.sync.max.u32 %0, %1, 0xffffffff;" : "=r"(out) : "r"(in))
#define REDUX_MIN(out, in) \
    asm volatile("redux.sync.min.u32 %0, %1, 0xffffffff;" : "=r"(out) : "r"(in))

#define STAGE_B 16384                      // 128 rows x 128 bytes
#define W5_SMEM (4 * STAGE_B + 128)        // 2 stages x 2 operands
#define TILE_PITCH 133
#define GR_SMEM (128 * TILE_PITCH * 4 + 256)  // transpose tile dominates

// mainloop: acc += A(128 x 64*kc) * B(128 x 64*kc)^T, both row-major bf16.
__device__ __forceinline__ void hmma_loop(char* sm, const char* Ag, const char* Bg,
                                          size_t strA, size_t strB, int kchunks,
                                          int tid, float acc[2][8][4]) {
    char* sA = sm;
    char* sB = sm + 2 * STAGE_B;
    int lane = tid & 31, wid = tid >> 5;
    int wm = wid & 3, wn = wid >> 2;
    int r = tid >> 3, cbyte = (tid & 7) * 16;
    uint32_t sA32 = smem_u32(sA), sB32 = smem_u32(sB);
    #pragma unroll
    for (int i = 0; i < 4; i++) {
        int row = r + 32 * i;
        uint32_t o = SWZ((uint32_t)(row * 128 + cbyte));
        CP_ASYNC16(sA32 + o, Ag + (size_t)row * strA + cbyte);
        CP_ASYNC16(sB32 + o, Bg + (size_t)row * strB + cbyte);
    }
    CP_COMMIT();
    CP_WAIT0();
    __syncthreads();
    int buf = 0;
    for (int c = 0; c < kchunks; c++) {
        if (c + 1 < kchunks) {
            const char* An = Ag + (size_t)(c + 1) * 128;
            const char* Bn = Bg + (size_t)(c + 1) * 128;
            uint32_t dA = sA32 + (buf ^ 1) * STAGE_B;
            uint32_t dB = sB32 + (buf ^ 1) * STAGE_B;
            #pragma unroll
            for (int i = 0; i < 4; i++) {
                int row = r + 32 * i;
                uint32_t o = SWZ((uint32_t)(row * 128 + cbyte));
                CP_ASYNC16(dA + o, An + (size_t)row * strA + cbyte);
                CP_ASYNC16(dB + o, Bn + (size_t)row * strB + cbyte);
            }
            CP_COMMIT();
        }
        uint32_t aB = sA32 + buf * STAGE_B, bB = sB32 + buf * STAGE_B;
        #pragma unroll
        for (int ks = 0; ks < 4; ks++) {
            uint32_t a[2][4], b[4][4];
            #pragma unroll
            for (int mi = 0; mi < 2; mi++) {
                int row = wm * 32 + mi * 16 + (lane & 15);
                int off = row * 128 + ks * 32 + ((lane >> 4) << 4);
                LDSM4(a[mi], aB + SWZ(off));
            }
            #pragma unroll
            for (int np = 0; np < 4; np++) {
                int row = wn * 64 + np * 16 + ((lane >> 4) << 3) + (lane & 7);
                int off = row * 128 + ks * 32 + (((lane >> 3) & 1) << 4);
                LDSM4(b[np], bB + SWZ(off));
            }
            #pragma unroll
            for (int mi = 0; mi < 2; mi++)
                #pragma unroll
                for (int nj = 0; nj < 8; nj++)
                    MMA16816(acc[mi][nj], a[mi], b[nj >> 1][(nj & 1) * 2], b[nj >> 1][(nj & 1) * 2 + 1]);
        }
        if (c + 1 < kchunks) {
            CP_WAIT0();
            __syncthreads();
            buf ^= 1;
        }
    }
}

// --------- Gram (triangular): stores fmono(2*X@X^T - xx_m - xx_n) bits -------
__global__ void __launch_bounds__(256, 2) gram_hmma(const __nv_bfloat16* __restrict__ Ae,
                                                    const __nv_bfloat16* __restrict__ Be,
                                                    const float* __restrict__ xx,
                                                    float* __restrict__ negd, int Kexp) {
    extern __shared__ char dsm[];
    uint32_t sb = smem_u32(dsm);
    char* sm = dsm + (((sb + 127) & ~127u) - sb);
    int tid = threadIdx.x, lane = tid & 31, wid = tid >> 5;
    int wm = wid & 3, wn = wid >> 2;
    int b = blockIdx.z;
    int rem = blockIdx.x, ti = 0;
    while (rem >= 16 - ti) { rem -= 16 - ti; ti++; }
    int tj = ti + rem;
    int m0 = ti * 128, n0 = tj * 128;

    float acc[2][8][4] = {};
    size_t str = (size_t)Kexp * 2;
    hmma_loop(sm, (const char*)(Ae + (size_t)(b * NPTS + m0) * Kexp),
                  (const char*)(Be + (size_t)(b * NPTS + n0) * Kexp),
              str, str, Kexp >> 6, tid, acc);

    const float* xxb = xx + b * NPTS;
    float* nd = negd + ((size_t)b << 22);
    float (*tile)[TILE_PITCH] = (float(*)[TILE_PITCH])sm;

    if (ti != tj) __syncthreads();

    #pragma unroll
    for (int mi = 0; mi < 2; mi++) {
        int lm0 = wm * 32 + mi * 16 + (lane >> 2);
        int rowa = m0 + lm0;
        float xm0 = __ldg(&xxb[rowa]), xm1 = __ldg(&xxb[rowa + 8]);
        #pragma unroll
        for (int nj = 0; nj < 8; nj++) {
            int ln = wn * 64 + nj * 8 + (lane & 3) * 2;
            int col = n0 + ln;
            float xn0 = __ldg(&xxb[col]), xn1 = __ldg(&xxb[col + 1]);
            float v00 = __uint_as_float(fmono(2.f * acc[mi][nj][0] - xm0 - xn0));
            float v01 = __uint_as_float(fmono(2.f * acc[mi][nj][1] - xm0 - xn1));
            float v10 = __uint_as_float(fmono(2.f * acc[mi][nj][2] - xm1 - xn0));
            float v11 = __uint_as_float(fmono(2.f * acc[mi][nj][3] - xm1 - xn1));
            *(float2*)&nd[(size_t)rowa * NPTS + col]       = make_float2(v00, v01);
            *(float2*)&nd[(size_t)(rowa + 8) * NPTS + col] = make_float2(v10, v11);
            if (ti != tj) {
                tile[lm0][ln]         = v00;
                tile[lm0][ln + 1]     = v01;
                tile[lm0 + 8][ln]     = v10;
                tile[lm0 + 8][ln + 1] = v11;
            }
        }
    }
    if (ti != tj) {
        __syncthreads();
        int nn = tid >> 1;
        int mmBase = (tid & 1) * 64;
        size_t gbase = (size_t)(n0 + nn) * NPTS + m0 + mmBase;
        #pragma unroll
        for (int k4 = 0; k4 < 16; k4++) {
            int mm = mmBase + k4 * 4;
            float4 w = make_float4(tile[mm][nn], tile[mm + 1][nn],
                                   tile[mm + 2][nn], tile[mm + 3][nn]);
            *(float4*)&nd[gbase + k4 * 4] = w;
        }
    }
}

// --------- W5: out = lrelu(cat@W5 * g + b), transposed store -----------------
__global__ void __launch_bounds__(256, 2) w5_hmma(const __nv_bfloat16* __restrict__ Ae,
                                                  const __nv_bfloat16* __restrict__ Be,
                                                  const float* __restrict__ g,
                                                  const float* __restrict__ bias,
                                                  float* __restrict__ out) {
    extern __shared__ char dsm[];
    uint32_t sb = smem_u32(dsm);
    char* sm = dsm + (((sb + 127) & ~127u) - sb);
    int tid = threadIdx.x, lane = tid & 31, wid = tid >> 5;
    int wm = wid & 3, wn = wid >> 2;
    int m0 = blockIdx.y * 128, n0 = blockIdx.x * 128;

    float acc[2][8][4] = {};
    hmma_loop(sm, (const char*)(Ae + (size_t)m0 * 1536),
                  (const char*)(Be + (size_t)n0 * 1536),
              3072, 3072, 24, tid, acc);

    #pragma unroll
    for (int mi = 0; mi < 2; mi++) {
        int m = m0 + wm * 32 + mi * 16 + (lane >> 2);
        #pragma unroll
        for (int half = 0; half < 2; half++) {
            int mr = m + half * 8;
            int bidx = mr >> 11, npt = mr & 2047;
            size_t obase = ((size_t)bidx << 10) * NPTS + npt;
            #pragma unroll
            for (int nj = 0; nj < 8; nj++) {
                int col = n0 + wn * 64 + nj * 8 + (lane & 3) * 2;
                float g0 = __ldg(&g[col]), g1 = __ldg(&g[col + 1]);
                float b0 = __ldg(&bias[col]), b1 = __ldg(&bias[col + 1]);
                float z0 = fmaf(acc[mi][nj][half * 2],     g0, b0);
                float z1 = fmaf(acc[mi][nj][half * 2 + 1], g1, b1);
                out[obase + (size_t)col * NPTS]       = z0 >= 0.f ? z0 : NEG_SLOPE * z0;
                out[obase + (size_t)(col + 1) * NPTS] = z1 >= 0.f ? z1 : NEG_SLOPE * z1;
            }
        }
    }
}

// ---------------- bf16x3 expansion kernels (Gram only) -----------------------
__global__ void expand_gram(const float* __restrict__ X, __nv_bfloat16* __restrict__ Ae,
                            __nv_bfloat16* __restrict__ Be, int K, int Kexp) {
    long long i = (long long)blockIdx.x * 256 + threadIdx.x;
    if (i >= (long long)NB * Kexp) return;
    int m = (int)(i / Kexp), k = (int)(i - (long long)m * Kexp);
    int t = (k < K) ? 0 : (k < 2 * K) ? 1 : (k < 3 * K) ? 2 : 3;
    __nv_bfloat16 av, bv;
    if (t == 3) { av = __float2bfloat16(0.f); bv = av; }
    else {
        float v = X[(size_t)m * K + (k - t * K)];
        __nv_bfloat16 hi = __float2bfloat16(v);
        __nv_bfloat16 lo = __float2bfloat16(v - __bfloat162float(hi));
        av = (t == 2) ? lo : hi;
        bv = (t == 1) ? lo : hi;
    }
    Ae[i] = av; Be[i] = bv;
}

__global__ void expand_cat(const float* __restrict__ X1, const float* __restrict__ X2,
                           const float* __restrict__ X3, const float* __restrict__ X4,
                           __nv_bfloat16* __restrict__ Ae) {
    long long i = (long long)blockIdx.x * 256 + threadIdx.x;   // NB*1536
    int m = (int)(i / 1536);
    int k = (int)(i - (long long)m * 1536);
    int t = k >> 9, k0 = k & 511;
    float v;
    if (k0 < 64)       v = X1[(size_t)m * 64 + k0];
    else if (k0 < 128) v = X2[(size_t)m * 64 + k0 - 64];
    else if (k0 < 256) v = X3[(size_t)m * 128 + k0 - 128];
    else               v = X4[(size_t)m * 256 + k0 - 256];
    __nv_bfloat16 hi = __float2bfloat16(v);
    Ae[i] = (t == 2) ? __float2bfloat16(v - __bfloat162float(hi)) : hi;
}

__global__ void expand_w5(const float* __restrict__ W, __nv_bfloat16* __restrict__ Be) {
    long long i = (long long)blockIdx.x * 256 + threadIdx.x;   // 1024*1536
    int n = (int)(i / 1536);
    int k = (int)(i - (long long)n * 1536);
    int t = k >> 9, k0 = k & 511;
    float v = W[(size_t)k0 * 1024 + n];
    __nv_bfloat16 hi = __float2bfloat16(v);
    Be[i] = (t == 1) ? __float2bfloat16(v - __bfloat162float(hi)) : hi;
}

// ---------------- squared norms ----------------------------------------------
__global__ void xx_kernel(const float* __restrict__ X, float* __restrict__ xx, int C) {
    int gw = (blockIdx.x * blockDim.x + threadIdx.x) >> 5;
    int lane = threadIdx.x & 31;
    if (gw >= NB) return;
    const float* row = X + (size_t)gw * C;
    float s = 0.f;
    for (int c = lane; c < C; c += 32) { float v = row[c]; s += v * v; }
    #pragma unroll
    for (int o = 16; o > 0; o >>= 1) s += __shfl_xor_sync(0xFFFFFFFFu, s, o);
    if (lane == 0) xx[gw] = s;
}

// ---------------- PC: fp32 SIMT 64x64 tiles, ascending-k (bit-exact) ---------
__global__ void __launch_bounds__(256) gemm_nn64(const float* __restrict__ A,
                                                 const float* __restrict__ B,
                                                 float* __restrict__ Cout,
                                                 int N, int Kdim) {
    __shared__ float As[2][8][68];
    __shared__ float Bs[2][8][68];
    int tid = threadIdx.x;
    int m0 = blockIdx.y * 64, n0 = blockIdx.x * 64;
    int tm = tid >> 4, tn = tid & 15;
    int la_m = tid >> 3, la_k = tid & 7;
    int lb_k = tid >> 6, lb_n = tid & 63;
    float acc[4][4] = {};
    float ra[2], rb[2];
    int kIters = (Kdim + 7) / 8;
    #pragma unroll
    for (int j = 0; j < 2; j++) {
        ra[j] = (la_k < Kdim) ? A[(size_t)(m0 + la_m + 32 * j) * Kdim + la_k] : 0.f;
        int kb = lb_k + 4 * j;
        rb[j] = (kb < Kdim) ? B[(size_t)kb * N + n0 + lb_n] : 0.f;
    }
    #pragma unroll
    for (int j = 0; j < 2; j++) {
        As[0][la_k][la_m + 32 * j] = ra[j];
        Bs[0][lb_k + 4 * j][lb_n] = rb[j];
    }
    __syncthreads();
    int buf = 0;
    for (int it = 0; it < kIters; ++it) {
        if (it + 1 < kIters) {
            int k0n = (it + 1) * 8;
            #pragma unroll
            for (int j = 0; j < 2; j++) {
                int ka = k0n + la_k;
                ra[j] = (ka < Kdim) ? A[(size_t)(m0 + la_m + 32 * j) * Kdim + ka] : 0.f;
                int kb = k0n + lb_k + 4 * j;
                rb[j] = (kb < Kdim) ? B[(size_t)kb * N + n0 + lb_n] : 0.f;
            }
        }
        #pragma unroll
        for (int k = 0; k < 8; k++) {
            float4 a4 = *(const float4*)&As[buf][k][tm * 4];
            float4 b4 = *(const float4*)&Bs[buf][k][tn * 4];
            float av[4] = {a4.x, a4.y, a4.z, a4.w};
            float bv[4] = {b4.x, b4.y, b4.z, b4.w};
            #pragma unroll
            for (int ii = 0; ii < 4; ii++)
                #pragma unroll
                for (int jj = 0; jj < 4; jj++)
                    acc[ii][jj] = fmaf(av[ii], bv[jj], acc[ii][jj]);
        }
        if (it + 1 < kIters) {
            #pragma unroll
            for (int j = 0; j < 2; j++) {
                As[buf ^ 1][la_k][la_m + 32 * j] = ra[j];
                Bs[buf ^ 1][lb_k + 4 * j][lb_n] = rb[j];
            }
        }
        __syncthreads();
        buf ^= 1;
    }
    #pragma unroll
    for (int ii = 0; ii < 4; ii++) {
        *(float4*)&Cout[(size_t)(m0 + tm * 4 + ii) * N + n0 + tn * 4] =
            make_float4(acc[ii][0], acc[ii][1], acc[ii][2], acc[ii][3]);
    }
}

// ---------------- top-20: early-exit threshold select -------------------------
#define CASD(x, y) { uint32_t hi = max(u[x], u[y]); uint32_t lo = min(u[x], u[y]); u[x] = hi; u[y] = lo; }
#define CASW(x, y) { uint32_t hi = max(w[x], w[y]); uint32_t lo = min(w[x], w[y]); w[x] = hi; w[y] = lo; }

__global__ void __launch_bounds__(256) topk_kernel(const uint32_t* __restrict__ negd,
                                                   int* __restrict__ idxout) {
    __shared__ uint32_t swv[160];
    __shared__ uint32_t s_L, s_T;
    __shared__ int s_ngt, s_neq;
    __shared__ int s_eq[64];
    int row = blockIdx.x, b = row >> 11, tid = threadIdx.x;
    int lane = tid & 31, wid = tid >> 5;
    const uint32_t* Grow = negd + (size_t)row * NPTS;
    // element i<4 -> index 4*tid+i ; i>=4 -> 1024 + 4*tid + (i-4)
    uint4 p0 = __ldg((const uint4*)Grow + tid);
    uint4 p1 = __ldg((const uint4*)(Grow + 1024) + tid);
    uint32_t uo[8] = {p0.x, p0.y, p0.z, p0.w, p1.x, p1.y, p1.z, p1.w};
    uint32_t u[8];
    #pragma unroll
    for (int i = 0; i < 8; i++) u[i] = uo[i];
    if (lane < KNN) swv[wid * KNN + lane] = 0;    // pad slots
    if (tid == 0) { s_ngt = 0; s_neq = 0; }
    // sort u desc (Batcher, 19 CAS)
    CASD(0,1) CASD(2,3) CASD(4,5) CASD(6,7)
    CASD(0,2) CASD(1,3) CASD(4,6) CASD(5,7)
    CASD(1,2) CASD(5,6)
    CASD(0,4) CASD(1,5) CASD(2,6) CASD(3,7)
    CASD(2,4) CASD(3,5)
    CASD(1,2) CASD(3,4) CASD(5,6)
    // phase A: 3 unconditional pops per warp
    #pragma unroll
    for (int r = 0; r < 3; r++) {
        uint32_t m;
        REDUX_MAX(m, u[0]);
        uint32_t bal = __ballot_sync(0xffffffffu, u[0] == m);
        if (lane == (int)(__ffs(bal) - 1)) {
            #pragma unroll
            for (int i = 0; i < 7; i++) u[i] = u[i + 1];
            u[7] = 0;
        }
        if (lane == 0) swv[wid * KNN + r] = m;
    }
    __syncthreads();
    // warp 0: L = 20th largest of the 24 phase-A candidates (= 5th smallest)
    if (wid == 0) {
        uint32_t c = 0xFFFFFFFFu;
        if (lane < 24) { int w8 = lane / 3; c = swv[w8 * KNN + (lane - w8 * 3)]; }
        uint32_t mn = 0;
        #pragma unroll
        for (int t = 0; t < 5; t++) {
            REDUX_MIN(mn, c);
            uint32_t bal = __ballot_sync(0xffffffffu, c == mn);
            if (lane == (int)(__ffs(bal) - 1)) c = 0xFFFFFFFFu;
        }
        if (lane == 0) s_L = mn;
    }
    __syncthreads();
    uint32_t L = s_L;
    // phase B: continue popping while warp max >= L (early exit), cap 20
    #pragma unroll 1
    for (int r = 3; r < KNN; r++) {
        uint32_t m;
        REDUX_MAX(m, u[0]);
        if (m < L) break;
        uint32_t bal = __ballot_sync(0xffffffffu, u[0] == m);
        if (lane == (int)(__ffs(bal) - 1)) {
            #pragma unroll
            for (int i = 0; i < 7; i++) u[i] = u[i + 1];
            u[7] = 0;
        }
        if (lane == 0) swv[wid * KNN + r] = m;
    }
    __syncthreads();
    // phase 2: warp 0 finds global T = 20th largest of the candidate union
    if (wid == 0) {
        uint32_t w[5];
        #pragma unroll
        for (int t = 0; t < 5; t++) w[t] = swv[lane + (t << 5)];
        CASW(0,1) CASW(3,4) CASW(2,4) CASW(2,3) CASW(1,4)
        CASW(0,3) CASW(0,2) CASW(1,3) CASW(1,2)
        uint32_t T = 0;
        #pragma unroll 1
        for (int r = 0; r < KNN; r++) {
            REDUX_MAX(T, w[0]);
            uint32_t bal = __ballot_sync(0xffffffffu, w[0] == T);
            if (lane == (int)(__ffs(bal) - 1)) {
                w[0] = w[1]; w[1] = w[2]; w[2] = w[3]; w[3] = w[4]; w[4] = 0;
            }
        }
        if (lane == 0) s_T = T;
    }
    __syncthreads();
    uint32_t T = s_T;
    int* outp = idxout + row * KNN;
    // compaction: strictly-greater unordered; equals resolved by smallest index
    #pragma unroll
    for (int i = 0; i < 8; i++) {
        uint32_t ui = uo[i];
        int idxl = (i < 4) ? (4 * tid + i) : (1024 + 4 * tid + (i - 4));
        if (ui > T) {
            int p = atomicAdd(&s_ngt, 1);
            outp[p] = (b << 11) + idxl;
        } else if (ui == T) {
            int p = atomicAdd(&s_neq, 1);
            if (p < 64) s_eq[p] = idxl;
        }
    }
    __syncthreads();
    if (tid == 0) {
        int ngt = s_ngt;
        int neq = s_neq < 64 ? s_neq : 64;
        int need = KNN - ngt;
        for (int t = 0; t < need; t++) {
            int bvv = 0x7fffffff, bi = 0;
            for (int q = 0; q < neq; q++)
                if (s_eq[q] < bvv) { bvv = s_eq[q]; bi = q; }
            s_eq[bi] = 0x7fffffff;
            outp[ngt + t] = (b << 11) + bvv;
        }
    }
}

// ---------------- gather + max/min + epilogue (float4) -----------------------
__global__ void gathermax4_kernel(const float* __restrict__ PC,
                                  const int* __restrict__ idx,
                                  const float* __restrict__ g,
                                  const float* __restrict__ bias,
                                  float* __restrict__ Xout, int cl) {
    int cout = 1 << cl;
    int i = blockIdx.x * 256 + threadIdx.x;
    int n = i >> (cl - 2);
    int d = (i & ((cout >> 2) - 1)) << 2;
    int ld = cout << 1;
    const int* ip = idx + n * KNN;
    float4 mx = make_float4(-FLT_MAX, -FLT_MAX, -FLT_MAX, -FLT_MAX);
    float4 mn = make_float4(FLT_MAX, FLT_MAX, FLT_MAX, FLT_MAX);
    #pragma unroll
    for (int k = 0; k < KNN; k++) {
        float4 v = *(const float4*)&PC[(size_t)__ldg(&ip[k]) * ld + d];
        mx.x = fmaxf(mx.x, v.x); mn.x = fminf(mn.x, v.x);
        mx.y = fmaxf(mx.y, v.y); mn.y = fminf(mn.y, v.y);
        mx.z = fmaxf(mx.z, v.z); mn.z = fminf(mn.z, v.z);
        mx.w = fmaxf(mx.w, v.w); mn.w = fminf(mn.w, v.w);
    }
    float4 Cc = *(const float4*)&PC[(size_t)n * ld + cout + d];
    float4 gd = *(const float4*)&g[d];
    float4 bd = *(const float4*)&bias[d];
    float4 o;
    float z;
    z = (gd.x >= 0.f ? mx.x : mn.x) + Cc.x; z = fmaf(gd.x, z, bd.x); o.x = z >= 0.f ? z : NEG_SLOPE * z;
    z = (gd.y >= 0.f ? mx.y : mn.y) + Cc.y; z = fmaf(gd.y, z, bd.y); o.y = z >= 0.f ? z : NEG_SLOPE * z;
    z = (gd.z >= 0.f ? mx.z : mn.z) + Cc.z; z = fmaf(gd.z, z, bd.z); o.z = z >= 0.f ? z : NEG_SLOPE * z;
    z = (gd.w >= 0.f ? mx.w : mn.w) + Cc.w; z = fmaf(gd.w, z, bd.w); o.w = z >= 0.f ? z : NEG_SLOPE * z;
    *(float4*)&Xout[(size_t)n * cout + d] = o;
}

// ---------------- combined weight: [W_a | W_b - W_a] -------------------------
__global__ void wcomb_kernel(const float* __restrict__ W, float* __restrict__ Wc,
                             int cin, int cout) {
    int i = blockIdx.x * 256 + threadIdx.x;
    int tot = cin * 2 * cout;
    if (i >= tot) return;
    int twoc = 2 * cout;
    int c = i / twoc, j = i - c * twoc;
    float v;
    if (j < cout) v = W[c * cout + j];
    else { int dd = j - cout; v = W[(cin + c) * cout + dd] - W[c * cout + dd]; }
    Wc[i] = v;
}

// ---------------- host launch -------------------------------------------------
extern "C" void kernel_launch(void* const* d_in, const int* in_sizes, int n_in,
                              void* d_out, int out_size) {
    (void)in_sizes; (void)n_in; (void)out_size;
    const float* pts = (const float*)d_in[0];
    const float* W[5]; const float* gg[5]; const float* bb[5];
    for (int i = 0; i < 5; i++) {
        W[i]  = (const float*)d_in[1 + 3 * i];
        gg[i] = (const float*)d_in[2 + 3 * i];
        bb[i] = (const float*)d_in[3 + 3 * i];
    }
    float* out = (float*)d_out;

    float *X1, *X2, *X3, *X4, *PC, *G, *XX, *WC; int* IDX;
    __nv_bfloat16 *XA, *XB, *CE, *WE;
    cudaGetSymbolAddress((void**)&X1, g_X1);
    cudaGetSymbolAddress((void**)&X2, g_X2);
    cudaGetSymbolAddress((void**)&X3, g_X3);
    cudaGetSymbolAddress((void**)&X4, g_X4);
    cudaGetSymbolAddress((void**)&PC, g_PC);
    cudaGetSymbolAddress((void**)&G,  g_G);
    cudaGetSymbolAddress((void**)&XX, g_xx);
    cudaGetSymbolAddress((void**)&WC, g_Wcomb);
    cudaGetSymbolAddress((void**)&IDX, g_idx);
    cudaGetSymbolAddress((void**)&XA, g_XexpA);
    cudaGetSymbolAddress((void**)&XB, g_XexpB);
    cudaGetSymbolAddress((void**)&CE, g_CATexp);
    cudaGetSymbolAddress((void**)&WE, g_W5exp);

    cudaFuncSetAttribute(gram_hmma, cudaFuncAttributeMaxDynamicSharedMemorySize, GR_SMEM);
    cudaFuncSetAttribute(w5_hmma,   cudaFuncAttributeMaxDynamicSharedMemorySize, W5_SMEM);

    struct L { const float* Xin; int cin, cout, cl, kexp; float* Xout; };
    L layers[4] = {
        { pts, 3,   64,  6, 64,  X1 },
        { X1,  64,  64,  6, 192, X2 },
        { X2,  64,  128, 7, 192, X3 },
        { X3,  128, 256, 8, 384, X4 },
    };
    for (int li = 0; li < 4; li++) {
        const L& l = layers[li];
        xx_kernel<<<NB / 8, 256>>>(l.Xin, XX, l.cin);
        long long etot = (long long)NB * l.kexp;
        expand_gram<<<(unsigned)((etot + 255) / 256), 256>>>(l.Xin, XA, XB, l.cin, l.kexp);
        gram_hmma<<<dim3(136, 1, BATCH), 256, GR_SMEM>>>(XA, XB, XX, G, l.kexp);
        topk_kernel<<<NB, 256>>>((const uint32_t*)G, IDX);
        int N2 = 2 * l.cout;
        int tot = l.cin * N2;
        wcomb_kernel<<<(tot + 255) / 256, 256>>>(W[li], WC, l.cin, l.cout);
        gemm_nn64<<<dim3(N2 / 64, NB / 64), 256>>>(l.Xin, WC, PC, N2, l.cin);
        gathermax4_kernel<<<(NB * l.cout / 4) / 256, 256>>>(PC, IDX, gg[li], bb[li], l.Xout, l.cl);
    }
    expand_cat<<<(unsigned)(((long long)NB * 1536 + 255) / 256), 256>>>(X1, X2, X3, X4, CE);
    expand_w5<<<(1024 * 1536) / 256, 256>>>(W[4], WE);
    w5_hmma<<<dim3(1024 / 128, NB / 128), 256, W5_SMEM>>>(CE, WE, gg[4], bb[4], out);
}